// round 10
// baseline (speedup 1.0000x reference)
#include <cuda_runtime.h>
#include <cuda_bf16.h>
#include <math.h>

#define T_STEPS 512
#define FUT     64
#define BATCH   1024
#define H       256
#define GRID    128
#define NTH     512
#define NTOT    (GRID * NTH)
#define CSZ     8
#define NCLUST  16

// ---------------- device state ----------------
// bf16 hi/lo pair planes: uint = 2 bf16 (low half = even/lower j). [b*128 + jpair]
__device__ __align__(16) unsigned d_h1p[2][2][BATCH * 128];  // [parity][hi/lo]
__device__ __align__(16) unsigned d_h2p[2][2][BATCH * 128];
__device__ __align__(16) unsigned d_c1p[2][BATCH * 128];     // [hi/lo]
__device__ __align__(16) unsigned d_c2p[2][BATCH * 128];
__device__ float d_h3[BATCH];
__device__ float d_c3[BATCH];

// Packed bf16 hi/lo weight fragments: [jgh(16)][kt(16)][nt(8)][lane(32)] uint4
__device__ uint4 d_Bp1 [16 * 16 * 8 * 32];
__device__ uint4 d_Bp2i[16 * 16 * 8 * 32];
__device__ uint4 d_Bp2h[16 * 16 * 8 * 32];

// per-cluster barriers + one global init barrier
__device__ unsigned d_cbcnt[NCLUST * 32];
__device__ volatile unsigned d_cbgen[NCLUST * 32];
__device__ unsigned d_gbcnt = 0;
__device__ volatile unsigned d_gbgen = 0;

__device__ __forceinline__ void cluster_bar(int bg) {
    __syncthreads();
    if (threadIdx.x == 0) {
        __threadfence();
        const int idx = bg * 32;
        unsigned g = d_cbgen[idx];
        if (atomicAdd(&d_cbcnt[idx], 1u) == CSZ - 1u) {
            atomicExch(&d_cbcnt[idx], 0u);
            __threadfence();
            d_cbgen[idx] = g + 1u;
        } else {
            while (d_cbgen[idx] == g) __nanosleep(32);
        }
        __threadfence();
    }
    __syncthreads();
}

__device__ __forceinline__ void global_bar() {
    __syncthreads();
    if (threadIdx.x == 0) {
        __threadfence();
        unsigned g = d_gbgen;
        if (atomicAdd(&d_gbcnt, 1u) == GRID - 1u) {
            atomicExch(&d_gbcnt, 0u);
            __threadfence();
            d_gbgen = g + 1u;
        } else {
            while (d_gbgen == g) __nanosleep(64);
        }
        __threadfence();
    }
    __syncthreads();
}

// HW tanh (1 MUFU). sigmoid via tanh identity (1 MUFU + 1 FMA).
__device__ __forceinline__ float tanh_ap(float z) {
    float r; asm("tanh.approx.f32 %0, %1;" : "=f"(r) : "f"(z)); return r;
}
__device__ __forceinline__ float sigf(float z)   { return fmaf(tanh_ap(0.5f * z), 0.5f, 0.5f); }
__device__ __forceinline__ float tanhf_(float z) { return tanh_ap(z); }

__device__ __forceinline__ void mma16816(float* c,
                                         unsigned a0, unsigned a1, unsigned a2, unsigned a3,
                                         unsigned b0, unsigned b1) {
    asm volatile("mma.sync.aligned.m16n8k16.row.col.f32.bf16.bf16.f32 "
                 "{%0,%1,%2,%3}, {%4,%5,%6,%7}, {%8,%9}, {%0,%1,%2,%3};"
                 : "+f"(c[0]), "+f"(c[1]), "+f"(c[2]), "+f"(c[3])
                 : "r"(a0), "r"(a1), "r"(a2), "r"(a3), "r"(b0), "r"(b1));
}

// Pure copy: pre-packed bf16 hi/lo planes (rows bg*64..) -> smem, stride 132 words.
__device__ __forceinline__ void stage_copy(unsigned* dhi, unsigned* dlo,
                                           const unsigned* shi, const unsigned* slo,
                                           int bg, int tid) {
    const uint4* gh = reinterpret_cast<const uint4*>(shi) + bg * 64 * 32;
    const uint4* gl = reinterpret_cast<const uint4*>(slo) + bg * 64 * 32;
    #pragma unroll
    for (int i = tid; i < 2048; i += NTH) {   // i = row*32 + c4
        int row = i >> 5, c4 = i & 31;
        uint4 vh = __ldcg(gh + i);
        uint4 vl = __ldcg(gl + i);
        *reinterpret_cast<uint4*>(dhi + row * 132 + c4 * 4) = vh;
        *reinterpret_cast<uint4*>(dlo + row * 132 + c4 * 4) = vl;
    }
}

// K=256 GEMM, quarter tile, register double-buffered B stream.
__device__ __forceinline__ void gemm256q(float (*acc)[4],
                                         const unsigned* sAhi, const unsigned* sAlo,
                                         const uint4* bb, int lane) {
    const int r = lane >> 2, c = lane & 3;
    const int i0 = r * 132 + c;
    const int i1 = (r + 8) * 132 + c;
    const uint4* bk0 = bb + lane;
    uint4 cur0 = bk0[0], cur1 = bk0[32], cur2 = bk0[64], cur3 = bk0[96];
    #pragma unroll
    for (int kt = 0; kt < 16; ++kt) {
        uint4 nxt0, nxt1, nxt2, nxt3;
        if (kt < 15) {
            const uint4* bn = bb + ((kt + 1) << 8) + lane;
            nxt0 = bn[0]; nxt1 = bn[32]; nxt2 = bn[64]; nxt3 = bn[96];
        }
        const int ko = kt * 8;
        unsigned ah0 = sAhi[i0 + ko],     ah1 = sAhi[i1 + ko];
        unsigned ah2 = sAhi[i0 + ko + 4], ah3 = sAhi[i1 + ko + 4];
        unsigned al0 = sAlo[i0 + ko],     al1 = sAlo[i1 + ko];
        unsigned al2 = sAlo[i0 + ko + 4], al3 = sAlo[i1 + ko + 4];
        mma16816(acc[0], ah0, ah1, ah2, ah3, cur0.x, cur0.y);
        mma16816(acc[0], al0, al1, al2, al3, cur0.x, cur0.y);
        mma16816(acc[0], ah0, ah1, ah2, ah3, cur0.z, cur0.w);
        mma16816(acc[1], ah0, ah1, ah2, ah3, cur1.x, cur1.y);
        mma16816(acc[1], al0, al1, al2, al3, cur1.x, cur1.y);
        mma16816(acc[1], ah0, ah1, ah2, ah3, cur1.z, cur1.w);
        mma16816(acc[2], ah0, ah1, ah2, ah3, cur2.x, cur2.y);
        mma16816(acc[2], al0, al1, al2, al3, cur2.x, cur2.y);
        mma16816(acc[2], ah0, ah1, ah2, ah3, cur2.z, cur2.w);
        mma16816(acc[3], ah0, ah1, ah2, ah3, cur3.x, cur3.y);
        mma16816(acc[3], al0, al1, al2, al3, cur3.x, cur3.y);
        mma16816(acc[3], ah0, ah1, ah2, ah3, cur3.z, cur3.w);
        if (kt < 15) { cur0 = nxt0; cur1 = nxt1; cur2 = nxt2; cur3 = nxt3; }
    }
}

__device__ __forceinline__ uint4 packw(const float* W, int u, int k0) {
    const float* wr = W + u * H;
    float w00 = wr[k0], w01 = wr[k0 + 1], w10 = wr[k0 + 8], w11 = wr[k0 + 9];
    __nv_bfloat162 h0 = __floats2bfloat162_rn(w00, w01);
    __nv_bfloat162 h1 = __floats2bfloat162_rn(w10, w11);
    __nv_bfloat162 l0 = __floats2bfloat162_rn(w00 - __bfloat162float(h0.x),
                                              w01 - __bfloat162float(h0.y));
    __nv_bfloat162 l1 = __floats2bfloat162_rn(w10 - __bfloat162float(h1.x),
                                              w11 - __bfloat162float(h1.y));
    uint4 rv;
    rv.x = *reinterpret_cast<unsigned*>(&h0);
    rv.y = *reinterpret_cast<unsigned*>(&h1);
    rv.z = *reinterpret_cast<unsigned*>(&l0);
    rv.w = *reinterpret_cast<unsigned*>(&l1);
    return rv;
}

__global__ void __launch_bounds__(NTH, 1) lstm_kernel(
    const float* __restrict__ x,
    const float* __restrict__ Wih1, const float* __restrict__ Whh1,
    const float* __restrict__ bih1, const float* __restrict__ bhh1,
    const float* __restrict__ Wih2, const float* __restrict__ Whh2,
    const float* __restrict__ bih2, const float* __restrict__ bhh2,
    const float* __restrict__ Wih3, const float* __restrict__ Whh3,
    const float* __restrict__ bih3, const float* __restrict__ bhh3,
    float* __restrict__ out)
{
    extern __shared__ unsigned smem_u[];
    unsigned* sAhi = smem_u;
    unsigned* sAlo = smem_u + 8448;      // 64*132
    unsigned* sBhi = smem_u + 16896;
    unsigned* sBlo = smem_u + 25344;
    float* s_c1 = reinterpret_cast<float*>(smem_u + 33792);  // 64*33
    float* s_c2 = s_c1 + 2112;
    float* s_b1 = s_c2 + 2112;
    float* s_w1 = s_b1 + 128;
    float* s_b2 = s_w1 + 128;

    const int tid   = threadIdx.x;
    const int lane  = tid & 31;
    const int warp  = tid >> 5;          // 0..15
    const int cta   = blockIdx.x;
    const int bg    = cta >> 3;          // 0..15 : 64-row batch group
    const int jg    = cta & 7;
    const int nq    = warp >> 2;         // 0..3 : 32-col quarter
    const int nhalf = nq >> 1;
    const int quad  = nq & 1;
    const int mrow  = (warp & 3) * 16;
    const int moff  = mrow * 132;
    const int jgh   = jg * 2 + nhalf;
    const int gtid  = cta * NTH + tid;

    const int q4 = lane & 3;
    const int rr = (q4 & 1) ? (lane >> 2) + 8 : (lane >> 2);
    const int rowb = mrow + rr;          // row within 64-tile (fixed per thread)
    const int b    = bg * 64 + rowb;     // global batch row (fixed per thread)

    // -------- init --------
    for (int i = gtid; i < BATCH * 128; i += NTOT) {
        d_h1p[0][0][i] = 0u; d_h1p[0][1][i] = 0u;
        d_h1p[1][0][i] = 0u; d_h1p[1][1][i] = 0u;
        d_h2p[0][0][i] = 0u; d_h2p[0][1][i] = 0u;
        d_h2p[1][0][i] = 0u; d_h2p[1][1][i] = 0u;
    }
    if (gtid < BATCH) { d_h3[gtid] = 0.f; d_c3[gtid] = 0.f; }
    for (int idx = gtid; idx < 16 * 16 * 8 * 32; idx += NTOT) {
        int lane_ = idx & 31, nt = (idx >> 5) & 7, kt = (idx >> 8) & 15, jh = idx >> 12;
        int jg_ = jh >> 1, hf = jh & 1;
        int n = lane_ >> 2, cq = lane_ & 3;
        int up = hf * 64 + nt * 8 + n;
        int u  = (up & 3) * 256 + jg_ * 32 + (up >> 2);
        int k0 = kt * 16 + cq * 2;
        d_Bp1 [idx] = packw(Whh1, u, k0);
        d_Bp2i[idx] = packw(Wih2, u, k0);
        d_Bp2h[idx] = packw(Whh2, u, k0);
    }
    for (int i = tid; i < 4224; i += NTH) s_c1[i] = 0.f;   // zeros s_c1 and s_c2
    if (tid < 128) {
        int jl = tid >> 2, g = tid & 3;
        int u = g * 256 + jg * 32 + jl;
        s_b1[tid] = bih1[u] + bhh1[u];
        s_w1[tid] = Wih1[u];
        s_b2[tid] = bih2[u] + bhh2[u];
    }
    global_bar();   // one-time; 128 CTAs co-resident

    int parity = 0;
    for (int t = 0; t < T_STEPS + FUT; ++t) {
        unsigned* h1n_hi = &d_h1p[parity ^ 1][0][0];
        unsigned* h1n_lo = &d_h1p[parity ^ 1][1][0];
        unsigned* h2n_hi = &d_h2p[parity ^ 1][0][0];
        unsigned* h2n_lo = &d_h2p[parity ^ 1][1][0];

        float acc2[4][4];   // h2*W_hh2 accumulator, lives across the phase-1 barrier

        // ================= phase 1 (+ hoisted gemm2h) =================
        stage_copy(sAhi, sAlo, &d_h1p[parity][0][0], &d_h1p[parity][1][0], bg, tid);
        stage_copy(sBhi, sBlo, &d_h2p[parity][0][0], &d_h2p[parity][1][0], bg, tid);
        __syncthreads();
        {
            const float xin = (t < T_STEPS) ? __ldg(x + t * BATCH + b) : __ldcg(d_c3 + b);

            float acc[4][4];
            #pragma unroll
            for (int nt = 0; nt < 4; ++nt)
                #pragma unroll
                for (int q = 0; q < 4; ++q) acc[nt][q] = 0.f;

            gemm256q(acc, sAhi + moff, sAlo + moff,
                     d_Bp1 + (jgh << 12) + quad * 128, lane);

            #pragma unroll
            for (int nt = 0; nt < 4; ++nt) {
                float s0 = __shfl_xor_sync(0xffffffffu, (q4 & 1) ? acc[nt][0] : acc[nt][2], 1);
                float s1 = __shfl_xor_sync(0xffffffffu, (q4 & 1) ? acc[nt][1] : acc[nt][3], 1);
                float gi, gf, gg, go;
                if (q4 & 1) { gi = s0; gf = s1; gg = acc[nt][2]; go = acc[nt][3]; }
                else        { gi = acc[nt][0]; gf = acc[nt][1]; gg = s0; go = s1; }
                int jl = nhalf * 16 + (quad * 4 + nt) * 2 + (q4 >> 1);
                float zi = gi + xin * s_w1[jl * 4 + 0] + s_b1[jl * 4 + 0];
                float zf = gf + xin * s_w1[jl * 4 + 1] + s_b1[jl * 4 + 1];
                float zg = gg + xin * s_w1[jl * 4 + 2] + s_b1[jl * 4 + 2];
                float zo = go + xin * s_w1[jl * 4 + 3] + s_b1[jl * 4 + 3];
                int sc = rowb * 33 + jl;
                float co = s_c1[sc];
                float cn = sigf(zf) * co + sigf(zi) * tanhf_(zg);
                float hn = sigf(zo) * tanhf_(cn);
                s_c1[sc] = cn;
                float cnp = __shfl_xor_sync(0xffffffffu, cn, 2);
                float hnp = __shfl_xor_sync(0xffffffffu, hn, 2);
                if ((q4 & 2) == 0) {
                    int jp = b * 128 + jg * 16 + nhalf * 8 + (quad * 4 + nt);
                    __nv_bfloat162 ch = __floats2bfloat162_rn(cn, cnp);
                    __nv_bfloat162 cl = __floats2bfloat162_rn(cn  - __bfloat162float(ch.x),
                                                              cnp - __bfloat162float(ch.y));
                    d_c1p[0][jp] = *reinterpret_cast<unsigned*>(&ch);
                    d_c1p[1][jp] = *reinterpret_cast<unsigned*>(&cl);
                    __nv_bfloat162 hh = __floats2bfloat162_rn(hn, hnp);
                    __nv_bfloat162 hl = __floats2bfloat162_rn(hn  - __bfloat162float(hh.x),
                                                              hnp - __bfloat162float(hh.y));
                    h1n_hi[jp] = *reinterpret_cast<unsigned*>(&hh);
                    h1n_lo[jp] = *reinterpret_cast<unsigned*>(&hl);
                }
            }

            // hoisted: h2 * W_hh2 (depends only on step t-1 data, staged in sB)
            #pragma unroll
            for (int nt = 0; nt < 4; ++nt)
                #pragma unroll
                for (int q = 0; q < 4; ++q) acc2[nt][q] = 0.f;
            gemm256q(acc2, sBhi + moff, sBlo + moff,
                     d_Bp2h + (jgh << 12) + quad * 128, lane);
        }
        cluster_bar(bg);

        // ================= phase 2 (only c1 * W_ih2 remains) =================
        stage_copy(sAhi, sAlo, &d_c1p[0][0], &d_c1p[1][0], bg, tid);
        __syncthreads();
        {
            gemm256q(acc2, sAhi + moff, sAlo + moff,
                     d_Bp2i + (jgh << 12) + quad * 128, lane);

            #pragma unroll
            for (int nt = 0; nt < 4; ++nt) {
                float s0 = __shfl_xor_sync(0xffffffffu, (q4 & 1) ? acc2[nt][0] : acc2[nt][2], 1);
                float s1 = __shfl_xor_sync(0xffffffffu, (q4 & 1) ? acc2[nt][1] : acc2[nt][3], 1);
                float gi, gf, gg, go;
                if (q4 & 1) { gi = s0; gf = s1; gg = acc2[nt][2]; go = acc2[nt][3]; }
                else        { gi = acc2[nt][0]; gf = acc2[nt][1]; gg = s0; go = s1; }
                int jl = nhalf * 16 + (quad * 4 + nt) * 2 + (q4 >> 1);
                float zi = gi + s_b2[jl * 4 + 0];
                float zf = gf + s_b2[jl * 4 + 1];
                float zg = gg + s_b2[jl * 4 + 2];
                float zo = go + s_b2[jl * 4 + 3];
                int sc = rowb * 33 + jl;
                float co = s_c2[sc];
                float cn = sigf(zf) * co + sigf(zi) * tanhf_(zg);
                float hn = sigf(zo) * tanhf_(cn);
                s_c2[sc] = cn;
                float cnp = __shfl_xor_sync(0xffffffffu, cn, 2);
                float hnp = __shfl_xor_sync(0xffffffffu, hn, 2);
                if ((q4 & 2) == 0) {
                    int jp = b * 128 + jg * 16 + nhalf * 8 + (quad * 4 + nt);
                    __nv_bfloat162 ch = __floats2bfloat162_rn(cn, cnp);
                    __nv_bfloat162 cl = __floats2bfloat162_rn(cn  - __bfloat162float(ch.x),
                                                              cnp - __bfloat162float(ch.y));
                    d_c2p[0][jp] = *reinterpret_cast<unsigned*>(&ch);
                    d_c2p[1][jp] = *reinterpret_cast<unsigned*>(&cl);
                    __nv_bfloat162 hh = __floats2bfloat162_rn(hn, hnp);
                    __nv_bfloat162 hl = __floats2bfloat162_rn(hn  - __bfloat162float(hh.x),
                                                              hnp - __bfloat162float(hh.y));
                    h2n_hi[jp] = *reinterpret_cast<unsigned*>(&hh);
                    h2n_lo[jp] = *reinterpret_cast<unsigned*>(&hl);
                }
            }
        }
        cluster_bar(bg);

        // ================= phase 3 (H=1), warps 0..7, one batch row each =================
        if (warp < 8) {
            int b3 = cta * 8 + warp;
            const unsigned* c2h = &d_c2p[0][b3 * 128];
            const unsigned* c2l = &d_c2p[1][b3 * 128];
            float a0 = 0.f, a1 = 0.f, a2 = 0.f, a3 = 0.f;
            #pragma unroll
            for (int kp_i = 0; kp_i < 4; ++kp_i) {
                int kp = kp_i * 32 + lane;
                unsigned vh = __ldcg(c2h + kp);
                unsigned vl = __ldcg(c2l + kp);
                __nv_bfloat162 bh = *reinterpret_cast<__nv_bfloat162*>(&vh);
                __nv_bfloat162 bl = *reinterpret_cast<__nv_bfloat162*>(&vl);
                float v0 = __bfloat162float(bh.x) + __bfloat162float(bl.x);
                float v1 = __bfloat162float(bh.y) + __bfloat162float(bl.y);
                int k0 = kp * 2;
                a0 = fmaf(v0, Wih3[0 * H + k0], fmaf(v1, Wih3[0 * H + k0 + 1], a0));
                a1 = fmaf(v0, Wih3[1 * H + k0], fmaf(v1, Wih3[1 * H + k0 + 1], a1));
                a2 = fmaf(v0, Wih3[2 * H + k0], fmaf(v1, Wih3[2 * H + k0 + 1], a2));
                a3 = fmaf(v0, Wih3[3 * H + k0], fmaf(v1, Wih3[3 * H + k0 + 1], a3));
            }
            #pragma unroll
            for (int o = 16; o > 0; o >>= 1) {
                a0 += __shfl_xor_sync(0xFFFFFFFFu, a0, o);
                a1 += __shfl_xor_sync(0xFFFFFFFFu, a1, o);
                a2 += __shfl_xor_sync(0xFFFFFFFFu, a2, o);
                a3 += __shfl_xor_sync(0xFFFFFFFFu, a3, o);
            }
            if (lane == 0) {
                float h3o = d_h3[b3], c3o = d_c3[b3];
                float zi = a0 + h3o * Whh3[0] + bih3[0] + bhh3[0];
                float zf = a1 + h3o * Whh3[1] + bih3[1] + bhh3[1];
                float zg = a2 + h3o * Whh3[2] + bih3[2] + bhh3[2];
                float zo = a3 + h3o * Whh3[3] + bih3[3] + bhh3[3];
                float cn = sigf(zf) * c3o + sigf(zi) * tanhf_(zg);
                float hn = sigf(zo) * tanhf_(cn);
                d_c3[b3] = cn;
                d_h3[b3] = hn;
                if (t >= T_STEPS) out[b3 * FUT + (t - T_STEPS)] = cn;
            }
        }
        // c3 is consumed by phase 1 only from t = T_STEPS onward
        if (t >= T_STEPS - 1) cluster_bar(bg);

        parity ^= 1;
    }
}

extern "C" void kernel_launch(void* const* d_in, const int* in_sizes, int n_in,
                              void* d_out, int out_size) {
    (void)in_sizes; (void)n_in; (void)out_size;
    const float* x    = (const float*)d_in[0];
    const float* Wih1 = (const float*)d_in[1];
    const float* Whh1 = (const float*)d_in[2];
    const float* bih1 = (const float*)d_in[3];
    const float* bhh1 = (const float*)d_in[4];
    const float* Wih2 = (const float*)d_in[5];
    const float* Whh2 = (const float*)d_in[6];
    const float* bih2 = (const float*)d_in[7];
    const float* bhh2 = (const float*)d_in[8];
    const float* Wih3 = (const float*)d_in[9];
    const float* Whh3 = (const float*)d_in[10];
    const float* bih3 = (const float*)d_in[11];
    const float* bhh3 = (const float*)d_in[12];

    const int smem_bytes = (4 * 64 * 132 + 2 * 2112 + 3 * 128) * 4;  // 153600
    cudaFuncSetAttribute(lstm_kernel, cudaFuncAttributeMaxDynamicSharedMemorySize, 153600);
    lstm_kernel<<<GRID, NTH, smem_bytes>>>(x, Wih1, Whh1, bih1, bhh1,
                                           Wih2, Whh2, bih2, bhh2,
                                           Wih3, Whh3, bih3, bhh3,
                                           (float*)d_out);
}

// round 11
// speedup vs baseline: 1.0101x; 1.0101x over previous
#include <cuda_runtime.h>
#include <cuda_bf16.h>
#include <math.h>

#define T_STEPS 512
#define FUT     64
#define BATCH   1024
#define H       256
#define GRID    128
#define NTH     1024
#define NTOT    (GRID * NTH)
#define CSZ     8
#define NCLUST  16

// ---------------- device state ----------------
// bf16 hi/lo pair planes: uint = 2 bf16 (low half = even j). [b*128 + jpair]
__device__ __align__(16) unsigned d_h1p[2][2][BATCH * 128];  // [parity][hi/lo]
__device__ __align__(16) unsigned d_h2p[2][2][BATCH * 128];
__device__ __align__(16) unsigned d_c1p[2][2][BATCH * 128];  // [parity][hi/lo]
__device__ __align__(16) unsigned d_c2p[2][2][BATCH * 128];
__device__ float d_h3[BATCH];
__device__ float d_c3[BATCH];

// Packed bf16 hi/lo weight fragments: [jgh(16)][kt(16)][nt(8)][lane(32)] uint4
__device__ uint4 d_Bp1 [16 * 16 * 8 * 32];
__device__ uint4 d_Bp2i[16 * 16 * 8 * 32];
__device__ uint4 d_Bp2h[16 * 16 * 8 * 32];

// per-cluster barriers + one global init barrier
__device__ unsigned d_cbcnt[NCLUST * 32];
__device__ volatile unsigned d_cbgen[NCLUST * 32];
__device__ unsigned d_gbcnt = 0;
__device__ volatile unsigned d_gbgen = 0;

__device__ __forceinline__ void cluster_bar(int bg) {
    __syncthreads();
    if (threadIdx.x == 0) {
        __threadfence();
        const int idx = bg * 32;
        unsigned g = d_cbgen[idx];
        if (atomicAdd(&d_cbcnt[idx], 1u) == CSZ - 1u) {
            atomicExch(&d_cbcnt[idx], 0u);
            __threadfence();
            d_cbgen[idx] = g + 1u;
        } else {
            while (d_cbgen[idx] == g) __nanosleep(32);
        }
        __threadfence();
    }
    __syncthreads();
}

__device__ __forceinline__ void global_bar() {
    __syncthreads();
    if (threadIdx.x == 0) {
        __threadfence();
        unsigned g = d_gbgen;
        if (atomicAdd(&d_gbcnt, 1u) == GRID - 1u) {
            atomicExch(&d_gbcnt, 0u);
            __threadfence();
            d_gbgen = g + 1u;
        } else {
            while (d_gbgen == g) __nanosleep(64);
        }
        __threadfence();
    }
    __syncthreads();
}

// HW tanh (1 MUFU). sigmoid via tanh identity (1 MUFU + 1 FMA).
__device__ __forceinline__ float tanh_ap(float z) {
    float r; asm("tanh.approx.f32 %0, %1;" : "=f"(r) : "f"(z)); return r;
}
__device__ __forceinline__ float sigf(float z)   { return fmaf(tanh_ap(0.5f * z), 0.5f, 0.5f); }
__device__ __forceinline__ float tanhf_(float z) { return tanh_ap(z); }

__device__ __forceinline__ void mma16816(float* c,
                                         unsigned a0, unsigned a1, unsigned a2, unsigned a3,
                                         unsigned b0, unsigned b1) {
    asm volatile("mma.sync.aligned.m16n8k16.row.col.f32.bf16.bf16.f32 "
                 "{%0,%1,%2,%3}, {%4,%5,%6,%7}, {%8,%9}, {%0,%1,%2,%3};"
                 : "+f"(c[0]), "+f"(c[1]), "+f"(c[2]), "+f"(c[3])
                 : "r"(a0), "r"(a1), "r"(a2), "r"(a3), "r"(b0), "r"(b1));
}

// Pure copy: pre-packed bf16 hi/lo planes (rows bg*64..) -> smem, stride 132 words.
__device__ __forceinline__ void stage_copy(unsigned* dhi, unsigned* dlo,
                                           const unsigned* shi, const unsigned* slo,
                                           int bg, int tid) {
    const uint4* gh = reinterpret_cast<const uint4*>(shi) + bg * 64 * 32;
    const uint4* gl = reinterpret_cast<const uint4*>(slo) + bg * 64 * 32;
    #pragma unroll
    for (int i = tid; i < 2048; i += NTH) {   // i = row*32 + c4
        int row = i >> 5, c4 = i & 31;
        uint4 vh = __ldcg(gh + i);
        uint4 vl = __ldcg(gl + i);
        *reinterpret_cast<uint4*>(dhi + row * 132 + c4 * 4) = vh;
        *reinterpret_cast<uint4*>(dlo + row * 132 + c4 * 4) = vl;
    }
}

// K=256 GEMM, 2 n-tiles (16 cols), ldmatrix A-loads, dual-buffered B stream.
// aAddr: per-lane shared byte address (hi plane, warp slice, ldmatrix pattern applied).
__device__ __forceinline__ void gemm2(float (*acc)[4], unsigned aAddr,
                                      const uint4* bb, int lane) {
    const uint4* bk = bb + lane;
    uint4 cur0 = bk[0], cur1 = bk[32];
    #pragma unroll
    for (int kt = 0; kt < 16; ++kt) {
        uint4 nxt0, nxt1;
        if (kt < 15) {
            const uint4* bn = bb + ((kt + 1) << 8) + lane;
            nxt0 = bn[0]; nxt1 = bn[32];
        }
        unsigned ah0, ah1, ah2, ah3, al0, al1, al2, al3;
        unsigned addr = aAddr + kt * 32;
        asm volatile("ldmatrix.sync.aligned.m8n8.x4.shared.b16 {%0,%1,%2,%3}, [%4];"
                     : "=r"(ah0), "=r"(ah1), "=r"(ah2), "=r"(ah3) : "r"(addr));
        asm volatile("ldmatrix.sync.aligned.m8n8.x4.shared.b16 {%0,%1,%2,%3}, [%4];"
                     : "=r"(al0), "=r"(al1), "=r"(al2), "=r"(al3) : "r"(addr + 33792));
        mma16816(acc[0], ah0, ah1, ah2, ah3, cur0.x, cur0.y);
        mma16816(acc[0], al0, al1, al2, al3, cur0.x, cur0.y);
        mma16816(acc[0], ah0, ah1, ah2, ah3, cur0.z, cur0.w);
        mma16816(acc[1], ah0, ah1, ah2, ah3, cur1.x, cur1.y);
        mma16816(acc[1], al0, al1, al2, al3, cur1.x, cur1.y);
        mma16816(acc[1], ah0, ah1, ah2, ah3, cur1.z, cur1.w);
        if (kt < 15) { cur0 = nxt0; cur1 = nxt1; }
    }
}

__device__ __forceinline__ uint4 packw(const float* W, int u, int k0) {
    const float* wr = W + u * H;
    float w00 = wr[k0], w01 = wr[k0 + 1], w10 = wr[k0 + 8], w11 = wr[k0 + 9];
    __nv_bfloat162 h0 = __floats2bfloat162_rn(w00, w01);
    __nv_bfloat162 h1 = __floats2bfloat162_rn(w10, w11);
    __nv_bfloat162 l0 = __floats2bfloat162_rn(w00 - __bfloat162float(h0.x),
                                              w01 - __bfloat162float(h0.y));
    __nv_bfloat162 l1 = __floats2bfloat162_rn(w10 - __bfloat162float(h1.x),
                                              w11 - __bfloat162float(h1.y));
    uint4 rv;
    rv.x = *reinterpret_cast<unsigned*>(&h0);
    rv.y = *reinterpret_cast<unsigned*>(&h1);
    rv.z = *reinterpret_cast<unsigned*>(&l0);
    rv.w = *reinterpret_cast<unsigned*>(&l1);
    return rv;
}

// layer-3 cell for one step; sel picks the c2 parity plane.
__device__ __forceinline__ void phase3(int t, int cta, int warp, int lane,
                                       const unsigned* c2h, const unsigned* c2l,
                                       const float* Wih3, const float* Whh3,
                                       const float* bih3, const float* bhh3,
                                       float* out) {
    if (warp >= 8) return;
    int b3 = cta * 8 + warp;
    float a0 = 0.f, a1 = 0.f, a2 = 0.f, a3 = 0.f;
    #pragma unroll
    for (int kp_i = 0; kp_i < 4; ++kp_i) {
        int kp = kp_i * 32 + lane;
        unsigned vh = __ldcg(c2h + b3 * 128 + kp);
        unsigned vl = __ldcg(c2l + b3 * 128 + kp);
        __nv_bfloat162 bh = *reinterpret_cast<__nv_bfloat162*>(&vh);
        __nv_bfloat162 bl = *reinterpret_cast<__nv_bfloat162*>(&vl);
        float v0 = __bfloat162float(bh.x) + __bfloat162float(bl.x);
        float v1 = __bfloat162float(bh.y) + __bfloat162float(bl.y);
        int k0 = kp * 2;
        a0 = fmaf(v0, Wih3[0 * H + k0], fmaf(v1, Wih3[0 * H + k0 + 1], a0));
        a1 = fmaf(v0, Wih3[1 * H + k0], fmaf(v1, Wih3[1 * H + k0 + 1], a1));
        a2 = fmaf(v0, Wih3[2 * H + k0], fmaf(v1, Wih3[2 * H + k0 + 1], a2));
        a3 = fmaf(v0, Wih3[3 * H + k0], fmaf(v1, Wih3[3 * H + k0 + 1], a3));
    }
    #pragma unroll
    for (int o = 16; o > 0; o >>= 1) {
        a0 += __shfl_xor_sync(0xFFFFFFFFu, a0, o);
        a1 += __shfl_xor_sync(0xFFFFFFFFu, a1, o);
        a2 += __shfl_xor_sync(0xFFFFFFFFu, a2, o);
        a3 += __shfl_xor_sync(0xFFFFFFFFu, a3, o);
    }
    if (lane == 0) {
        float h3o = d_h3[b3], c3o = d_c3[b3];
        float zi = a0 + h3o * Whh3[0] + bih3[0] + bhh3[0];
        float zf = a1 + h3o * Whh3[1] + bih3[1] + bhh3[1];
        float zg = a2 + h3o * Whh3[2] + bih3[2] + bhh3[2];
        float zo = a3 + h3o * Whh3[3] + bih3[3] + bhh3[3];
        float cn = sigf(zf) * c3o + sigf(zi) * tanhf_(zg);
        float hn = sigf(zo) * tanhf_(cn);
        d_c3[b3] = cn;
        d_h3[b3] = hn;
        if (t >= T_STEPS) out[b3 * FUT + (t - T_STEPS)] = cn;
    }
}

__global__ void __launch_bounds__(NTH, 1) lstm_kernel(
    const float* __restrict__ x,
    const float* __restrict__ Wih1, const float* __restrict__ Whh1,
    const float* __restrict__ bih1, const float* __restrict__ bhh1,
    const float* __restrict__ Wih2, const float* __restrict__ Whh2,
    const float* __restrict__ bih2, const float* __restrict__ bhh2,
    const float* __restrict__ Wih3, const float* __restrict__ Whh3,
    const float* __restrict__ bih3, const float* __restrict__ bhh3,
    float* __restrict__ out)
{
    extern __shared__ unsigned smem_u[];
    unsigned* sAhi = smem_u;                 // word offsets: 0, 8448, 16896, 25344
    unsigned* sAlo = smem_u + 8448;
    unsigned* sBhi = smem_u + 16896;
    unsigned* sBlo = smem_u + 25344;
    float* s_c1 = reinterpret_cast<float*>(smem_u + 33792);  // 64*33
    float* s_c2 = s_c1 + 2112;
    float* s_b1 = s_c2 + 2112;
    float* s_w1 = s_b1 + 128;
    float* s_b2 = s_w1 + 128;

    unsigned smem_base;
    asm("{ .reg .u64 t1; cvta.to.shared.u64 t1, %1; cvt.u32.u64 %0, t1; }"
        : "=r"(smem_base) : "l"(smem_u));

    const int tid   = threadIdx.x;
    const int lane  = tid & 31;
    const int warp  = tid >> 5;          // 0..31
    const int cta   = blockIdx.x;
    const int bg    = cta >> 3;          // 0..15 : 64-row batch group
    const int jg    = cta & 7;
    const int mrow  = (warp & 3) * 16;
    const int wq    = warp >> 2;         // 0..7
    const int nhalf = wq >> 2;           // 0..1
    const int q2    = wq & 3;            // 0..3 : 16-col slice within half
    const int jgh   = jg * 2 + nhalf;
    const int gtid  = cta * NTH + tid;

    // ldmatrix per-lane address pattern within the warp's 16-row A slice
    const unsigned lpat = (unsigned)((lane & 15) * 528 + (lane >> 4) * 16);
    const unsigned addrA = smem_base + mrow * 528 + lpat;            // sA planes
    const unsigned addrB = smem_base + 16896 * 4 + mrow * 528 + lpat; // sB planes
    const int boff = (jgh << 12) + q2 * 64;   // uint4 offset into weight arrays

    const int q4 = lane & 3;
    const int rr = (q4 & 1) ? (lane >> 2) + 8 : (lane >> 2);
    const int rowb = mrow + rr;
    const int b    = bg * 64 + rowb;

    // -------- init --------
    for (int i = gtid; i < BATCH * 128; i += NTOT) {
        d_h1p[0][0][i] = 0u; d_h1p[0][1][i] = 0u;
        d_h1p[1][0][i] = 0u; d_h1p[1][1][i] = 0u;
        d_h2p[0][0][i] = 0u; d_h2p[0][1][i] = 0u;
        d_h2p[1][0][i] = 0u; d_h2p[1][1][i] = 0u;
    }
    if (gtid < BATCH) { d_h3[gtid] = 0.f; d_c3[gtid] = 0.f; }
    for (int idx = gtid; idx < 16 * 16 * 8 * 32; idx += NTOT) {
        int lane_ = idx & 31, nt = (idx >> 5) & 7, kt = (idx >> 8) & 15, jh = idx >> 12;
        int jg_ = jh >> 1, hf = jh & 1;
        int n = lane_ >> 2, cq = lane_ & 3;
        int up = hf * 64 + nt * 8 + n;
        int u  = (up & 3) * 256 + jg_ * 32 + (up >> 2);
        int k0 = kt * 16 + cq * 2;
        d_Bp1 [idx] = packw(Whh1, u, k0);
        d_Bp2i[idx] = packw(Wih2, u, k0);
        d_Bp2h[idx] = packw(Whh2, u, k0);
    }
    for (int i = tid; i < 4224; i += NTH) s_c1[i] = 0.f;   // zeros s_c1 and s_c2
    if (tid < 128) {
        int jl = tid >> 2, g = tid & 3;
        int u = g * 256 + jg * 32 + jl;
        s_b1[tid] = bih1[u] + bhh1[u];
        s_w1[tid] = Wih1[u];
        s_b2[tid] = bih2[u] + bhh2[u];
    }
    global_bar();   // one-time; 128 CTAs co-resident

    int parity = 0;
    for (int t = 0; t < T_STEPS + FUT; ++t) {
        // ================= PH-A: layer-1 =================
        stage_copy(sAhi, sAlo, &d_h1p[parity][0][0], &d_h1p[parity][1][0], bg, tid);
        __syncthreads();
        {
            const float xin = (t < T_STEPS) ? __ldg(x + t * BATCH + b) : __ldcg(d_c3 + b);

            float acc[2][4];
            #pragma unroll
            for (int nt = 0; nt < 2; ++nt)
                #pragma unroll
                for (int q = 0; q < 4; ++q) acc[nt][q] = 0.f;

            gemm2(acc, addrA, d_Bp1 + boff, lane);

            #pragma unroll
            for (int nt = 0; nt < 2; ++nt) {
                float s0 = __shfl_xor_sync(0xffffffffu, (q4 & 1) ? acc[nt][0] : acc[nt][2], 1);
                float s1 = __shfl_xor_sync(0xffffffffu, (q4 & 1) ? acc[nt][1] : acc[nt][3], 1);
                float gi, gf, gg, go;
                if (q4 & 1) { gi = s0; gf = s1; gg = acc[nt][2]; go = acc[nt][3]; }
                else        { gi = acc[nt][0]; gf = acc[nt][1]; gg = s0; go = s1; }
                int ntg = q2 * 2 + nt;
                int jl  = nhalf * 16 + ntg * 2 + (q4 >> 1);
                float zi = gi + xin * s_w1[jl * 4 + 0] + s_b1[jl * 4 + 0];
                float zf = gf + xin * s_w1[jl * 4 + 1] + s_b1[jl * 4 + 1];
                float zg = gg + xin * s_w1[jl * 4 + 2] + s_b1[jl * 4 + 2];
                float zo = go + xin * s_w1[jl * 4 + 3] + s_b1[jl * 4 + 3];
                int sc = rowb * 33 + jl;
                float co = s_c1[sc];
                float cn = sigf(zf) * co + sigf(zi) * tanhf_(zg);
                float hn = sigf(zo) * tanhf_(cn);
                s_c1[sc] = cn;
                float cnp = __shfl_xor_sync(0xffffffffu, cn, 2);
                float hnp = __shfl_xor_sync(0xffffffffu, hn, 2);
                if ((q4 & 2) == 0) {
                    int jp = b * 128 + jg * 16 + nhalf * 8 + ntg;
                    __nv_bfloat162 ch = __floats2bfloat162_rn(cn, cnp);
                    __nv_bfloat162 cl = __floats2bfloat162_rn(cn  - __bfloat162float(ch.x),
                                                              cnp - __bfloat162float(ch.y));
                    d_c1p[parity ^ 1][0][jp] = *reinterpret_cast<unsigned*>(&ch);
                    d_c1p[parity ^ 1][1][jp] = *reinterpret_cast<unsigned*>(&cl);
                    __nv_bfloat162 hh = __floats2bfloat162_rn(hn, hnp);
                    __nv_bfloat162 hl = __floats2bfloat162_rn(hn  - __bfloat162float(hh.x),
                                                              hnp - __bfloat162float(hh.y));
                    d_h1p[parity ^ 1][0][jp] = *reinterpret_cast<unsigned*>(&hh);
                    d_h1p[parity ^ 1][1][jp] = *reinterpret_cast<unsigned*>(&hl);
                }
            }
        }
        cluster_bar(bg);   // the ONLY per-step barrier in the main phase

        // ================= PH-B: layer-2 (+ deferred layer-3) =================
        stage_copy(sAhi, sAlo, &d_c1p[parity ^ 1][0][0], &d_c1p[parity ^ 1][1][0], bg, tid);
        stage_copy(sBhi, sBlo, &d_h2p[parity][0][0], &d_h2p[parity][1][0], bg, tid);
        __syncthreads();
        {
            float acc[2][4];
            #pragma unroll
            for (int nt = 0; nt < 2; ++nt)
                #pragma unroll
                for (int q = 0; q < 4; ++q) acc[nt][q] = 0.f;

            gemm2(acc, addrB, d_Bp2h + boff, lane);
            gemm2(acc, addrA, d_Bp2i + boff, lane);

            #pragma unroll
            for (int nt = 0; nt < 2; ++nt) {
                float s0 = __shfl_xor_sync(0xffffffffu, (q4 & 1) ? acc[nt][0] : acc[nt][2], 1);
                float s1 = __shfl_xor_sync(0xffffffffu, (q4 & 1) ? acc[nt][1] : acc[nt][3], 1);
                float gi, gf, gg, go;
                if (q4 & 1) { gi = s0; gf = s1; gg = acc[nt][2]; go = acc[nt][3]; }
                else        { gi = acc[nt][0]; gf = acc[nt][1]; gg = s0; go = s1; }
                int ntg = q2 * 2 + nt;
                int jl  = nhalf * 16 + ntg * 2 + (q4 >> 1);
                float zi = gi + s_b2[jl * 4 + 0];
                float zf = gf + s_b2[jl * 4 + 1];
                float zg = gg + s_b2[jl * 4 + 2];
                float zo = go + s_b2[jl * 4 + 3];
                int sc = rowb * 33 + jl;
                float co = s_c2[sc];
                float cn = sigf(zf) * co + sigf(zi) * tanhf_(zg);
                float hn = sigf(zo) * tanhf_(cn);
                s_c2[sc] = cn;
                float cnp = __shfl_xor_sync(0xffffffffu, cn, 2);
                float hnp = __shfl_xor_sync(0xffffffffu, hn, 2);
                if ((q4 & 2) == 0) {
                    int jp = b * 128 + jg * 16 + nhalf * 8 + ntg;
                    __nv_bfloat162 ch = __floats2bfloat162_rn(cn, cnp);
                    __nv_bfloat162 cl = __floats2bfloat162_rn(cn  - __bfloat162float(ch.x),
                                                              cnp - __bfloat162float(ch.y));
                    d_c2p[parity ^ 1][0][jp] = *reinterpret_cast<unsigned*>(&ch);
                    d_c2p[parity ^ 1][1][jp] = *reinterpret_cast<unsigned*>(&cl);
                    __nv_bfloat162 hh = __floats2bfloat162_rn(hn, hnp);
                    __nv_bfloat162 hl = __floats2bfloat162_rn(hn  - __bfloat162float(hh.x),
                                                              hnp - __bfloat162float(hh.y));
                    d_h2p[parity ^ 1][0][jp] = *reinterpret_cast<unsigned*>(&hh);
                    d_h2p[parity ^ 1][1][jp] = *reinterpret_cast<unsigned*>(&hl);
                }
            }
        }

        // deferred layer-3 for step t-1 (reads c2(t-1) = c2p[parity]; never outputs)
        if (t >= 1 && t <= T_STEPS - 1)
            phase3(t - 1, cta, warp, lane,
                   &d_c2p[parity][0][0], &d_c2p[parity][1][0],
                   Wih3, Whh3, bih3, bhh3, out);

        // future region: layer-3 must be current-step (c3 feeds next step's layer-1)
        if (t >= T_STEPS - 1) {
            cluster_bar(bg);
            phase3(t, cta, warp, lane,
                   &d_c2p[parity ^ 1][0][0], &d_c2p[parity ^ 1][1][0],
                   Wih3, Whh3, bih3, bhh3, out);
            cluster_bar(bg);
        }

        parity ^= 1;
    }
}

extern "C" void kernel_launch(void* const* d_in, const int* in_sizes, int n_in,
                              void* d_out, int out_size) {
    (void)in_sizes; (void)n_in; (void)out_size;
    const float* x    = (const float*)d_in[0];
    const float* Wih1 = (const float*)d_in[1];
    const float* Whh1 = (const float*)d_in[2];
    const float* bih1 = (const float*)d_in[3];
    const float* bhh1 = (const float*)d_in[4];
    const float* Wih2 = (const float*)d_in[5];
    const float* Whh2 = (const float*)d_in[6];
    const float* bih2 = (const float*)d_in[7];
    const float* bhh2 = (const float*)d_in[8];
    const float* Wih3 = (const float*)d_in[9];
    const float* Whh3 = (const float*)d_in[10];
    const float* bih3 = (const float*)d_in[11];
    const float* bhh3 = (const float*)d_in[12];

    const int smem_bytes = (4 * 8448 + 2 * 2112 + 3 * 128) * 4;  // 153600
    cudaFuncSetAttribute(lstm_kernel, cudaFuncAttributeMaxDynamicSharedMemorySize, 153600);
    lstm_kernel<<<GRID, NTH, smem_bytes>>>(x, Wih1, Whh1, bih1, bhh1,
                                           Wih2, Whh2, bih2, bhh2,
                                           Wih3, Whh3, bih3, bhh3,
                                           (float*)d_out);
}

// round 12
// speedup vs baseline: 1.0288x; 1.0185x over previous
#include <cuda_runtime.h>
#include <cuda_bf16.h>
#include <math.h>

#define T_STEPS 512
#define FUT     64
#define BATCH   1024
#define H       256
#define GRID    128
#define NTH     512
#define NTOT    (GRID * NTH)
#define CSZ     8
#define NCLUST  16

// ---------------- device state ----------------
// bf16 hi/lo pair planes: uint = 2 bf16 (low half = even/lower j). [b*128 + jpair]
__device__ __align__(16) unsigned d_h1p[2][2][BATCH * 128];  // [parity][hi/lo]
__device__ __align__(16) unsigned d_h2p[2][2][BATCH * 128];
__device__ __align__(16) unsigned d_c1p[2][BATCH * 128];     // [hi/lo]
__device__ __align__(16) unsigned d_c2p[2][BATCH * 128];
__device__ float d_h3[BATCH];
__device__ float d_c3[BATCH];

// Packed bf16 hi/lo weight fragments: [jgh(16)][kt(16)][nt(8)][lane(32)] uint4
__device__ uint4 d_Bp1 [16 * 16 * 8 * 32];
__device__ uint4 d_Bp2i[16 * 16 * 8 * 32];
__device__ uint4 d_Bp2h[16 * 16 * 8 * 32];

// per-cluster barriers + one global init barrier
__device__ unsigned d_cbcnt[NCLUST * 32];
__device__ volatile unsigned d_cbgen[NCLUST * 32];
__device__ unsigned d_gbcnt = 0;
__device__ volatile unsigned d_gbgen = 0;

__device__ __forceinline__ void cluster_bar(int bg) {
    __syncthreads();
    if (threadIdx.x == 0) {
        __threadfence();
        const int idx = bg * 32;
        unsigned g = d_cbgen[idx];
        if (atomicAdd(&d_cbcnt[idx], 1u) == CSZ - 1u) {
            atomicExch(&d_cbcnt[idx], 0u);
            __threadfence();
            d_cbgen[idx] = g + 1u;
        } else {
            while (d_cbgen[idx] == g) __nanosleep(32);
        }
        __threadfence();
    }
    __syncthreads();
}

__device__ __forceinline__ void global_bar() {
    __syncthreads();
    if (threadIdx.x == 0) {
        __threadfence();
        unsigned g = d_gbgen;
        if (atomicAdd(&d_gbcnt, 1u) == GRID - 1u) {
            atomicExch(&d_gbcnt, 0u);
            __threadfence();
            d_gbgen = g + 1u;
        } else {
            while (d_gbgen == g) __nanosleep(64);
        }
        __threadfence();
    }
    __syncthreads();
}

// HW tanh (1 MUFU). sigmoid via tanh identity (1 MUFU + 1 FMA).
__device__ __forceinline__ float tanh_ap(float z) {
    float r; asm("tanh.approx.f32 %0, %1;" : "=f"(r) : "f"(z)); return r;
}
__device__ __forceinline__ float sigf(float z)   { return fmaf(tanh_ap(0.5f * z), 0.5f, 0.5f); }
__device__ __forceinline__ float tanhf_(float z) { return tanh_ap(z); }

__device__ __forceinline__ void mma16816(float* c,
                                         unsigned a0, unsigned a1, unsigned a2, unsigned a3,
                                         unsigned b0, unsigned b1) {
    asm volatile("mma.sync.aligned.m16n8k16.row.col.f32.bf16.bf16.f32 "
                 "{%0,%1,%2,%3}, {%4,%5,%6,%7}, {%8,%9}, {%0,%1,%2,%3};"
                 : "+f"(c[0]), "+f"(c[1]), "+f"(c[2]), "+f"(c[3])
                 : "r"(a0), "r"(a1), "r"(a2), "r"(a3), "r"(b0), "r"(b1));
}

// Pure copy: pre-packed bf16 hi/lo planes (rows bg*64..) -> smem, stride 132 words.
__device__ __forceinline__ void stage_copy(unsigned* dhi, unsigned* dlo,
                                           const unsigned* shi, const unsigned* slo,
                                           int bg, int tid) {
    const uint4* gh = reinterpret_cast<const uint4*>(shi) + bg * 64 * 32;
    const uint4* gl = reinterpret_cast<const uint4*>(slo) + bg * 64 * 32;
    #pragma unroll
    for (int i = tid; i < 2048; i += NTH) {   // i = row*32 + c4
        int row = i >> 5, c4 = i & 31;
        uint4 vh = __ldcg(gh + i);
        uint4 vl = __ldcg(gl + i);
        *reinterpret_cast<uint4*>(dhi + row * 132 + c4 * 4) = vh;
        *reinterpret_cast<uint4*>(dlo + row * 132 + c4 * 4) = vl;
    }
}

// K=256 GEMM, quarter tile, DEPTH-3 register-ring B prefetch.
__device__ __forceinline__ void gemm256q(float (*acc)[4],
                                         const unsigned* sAhi, const unsigned* sAlo,
                                         const uint4* bb, int lane) {
    const int r = lane >> 2, c = lane & 3;
    const int i0 = r * 132 + c;
    const int i1 = (r + 8) * 132 + c;
    uint4 buf[3][4];
    #pragma unroll
    for (int s = 0; s < 3; ++s) {
        const uint4* bk = bb + (s << 8) + lane;
        buf[s][0] = bk[0]; buf[s][1] = bk[32]; buf[s][2] = bk[64]; buf[s][3] = bk[96];
    }
    #pragma unroll
    for (int kt = 0; kt < 16; ++kt) {
        uint4 nv0, nv1, nv2, nv3;
        if (kt < 13) {
            const uint4* bn = bb + ((kt + 3) << 8) + lane;
            nv0 = bn[0]; nv1 = bn[32]; nv2 = bn[64]; nv3 = bn[96];
        }
        const int ko = kt * 8;
        unsigned ah0 = sAhi[i0 + ko],     ah1 = sAhi[i1 + ko];
        unsigned ah2 = sAhi[i0 + ko + 4], ah3 = sAhi[i1 + ko + 4];
        unsigned al0 = sAlo[i0 + ko],     al1 = sAlo[i1 + ko];
        unsigned al2 = sAlo[i0 + ko + 4], al3 = sAlo[i1 + ko + 4];
        uint4* cur = buf[kt % 3];          // fully unrolled -> static index
        mma16816(acc[0], ah0, ah1, ah2, ah3, cur[0].x, cur[0].y);
        mma16816(acc[0], al0, al1, al2, al3, cur[0].x, cur[0].y);
        mma16816(acc[0], ah0, ah1, ah2, ah3, cur[0].z, cur[0].w);
        mma16816(acc[1], ah0, ah1, ah2, ah3, cur[1].x, cur[1].y);
        mma16816(acc[1], al0, al1, al2, al3, cur[1].x, cur[1].y);
        mma16816(acc[1], ah0, ah1, ah2, ah3, cur[1].z, cur[1].w);
        mma16816(acc[2], ah0, ah1, ah2, ah3, cur[2].x, cur[2].y);
        mma16816(acc[2], al0, al1, al2, al3, cur[2].x, cur[2].y);
        mma16816(acc[2], ah0, ah1, ah2, ah3, cur[2].z, cur[2].w);
        mma16816(acc[3], ah0, ah1, ah2, ah3, cur[3].x, cur[3].y);
        mma16816(acc[3], al0, al1, al2, al3, cur[3].x, cur[3].y);
        mma16816(acc[3], ah0, ah1, ah2, ah3, cur[3].z, cur[3].w);
        if (kt < 13) {
            cur[0] = nv0; cur[1] = nv1; cur[2] = nv2; cur[3] = nv3;
        }
    }
}

__device__ __forceinline__ uint4 packw(const float* W, int u, int k0) {
    const float* wr = W + u * H;
    float w00 = wr[k0], w01 = wr[k0 + 1], w10 = wr[k0 + 8], w11 = wr[k0 + 9];
    __nv_bfloat162 h0 = __floats2bfloat162_rn(w00, w01);
    __nv_bfloat162 h1 = __floats2bfloat162_rn(w10, w11);
    __nv_bfloat162 l0 = __floats2bfloat162_rn(w00 - __bfloat162float(h0.x),
                                              w01 - __bfloat162float(h0.y));
    __nv_bfloat162 l1 = __floats2bfloat162_rn(w10 - __bfloat162float(h1.x),
                                              w11 - __bfloat162float(h1.y));
    uint4 rv;
    rv.x = *reinterpret_cast<unsigned*>(&h0);
    rv.y = *reinterpret_cast<unsigned*>(&h1);
    rv.z = *reinterpret_cast<unsigned*>(&l0);
    rv.w = *reinterpret_cast<unsigned*>(&l1);
    return rv;
}

__global__ void __launch_bounds__(NTH, 1) lstm_kernel(
    const float* __restrict__ x,
    const float* __restrict__ Wih1, const float* __restrict__ Whh1,
    const float* __restrict__ bih1, const float* __restrict__ bhh1,
    const float* __restrict__ Wih2, const float* __restrict__ Whh2,
    const float* __restrict__ bih2, const float* __restrict__ bhh2,
    const float* __restrict__ Wih3, const float* __restrict__ Whh3,
    const float* __restrict__ bih3, const float* __restrict__ bhh3,
    float* __restrict__ out)
{
    extern __shared__ unsigned smem_u[];
    unsigned* sAhi = smem_u;
    unsigned* sAlo = smem_u + 8448;      // 64*132
    unsigned* sBhi = smem_u + 16896;
    unsigned* sBlo = smem_u + 25344;
    float* s_c1 = reinterpret_cast<float*>(smem_u + 33792);  // 64*33
    float* s_c2 = s_c1 + 2112;
    float* s_b1 = s_c2 + 2112;
    float* s_w1 = s_b1 + 128;
    float* s_b2 = s_w1 + 128;

    const int tid   = threadIdx.x;
    const int lane  = tid & 31;
    const int warp  = tid >> 5;          // 0..15
    const int cta   = blockIdx.x;
    const int bg    = cta >> 3;          // 0..15 : 64-row batch group
    const int jg    = cta & 7;
    const int nq    = warp >> 2;         // 0..3 : 32-col quarter
    const int nhalf = nq >> 1;
    const int quad  = nq & 1;
    const int mrow  = (warp & 3) * 16;
    const int moff  = mrow * 132;
    const int jgh   = jg * 2 + nhalf;
    const int gtid  = cta * NTH + tid;

    const int q4 = lane & 3;
    const int rr = (q4 & 1) ? (lane >> 2) + 8 : (lane >> 2);
    const int rowb = mrow + rr;
    const int b    = bg * 64 + rowb;

    // -------- init --------
    for (int i = gtid; i < BATCH * 128; i += NTOT) {
        d_h1p[0][0][i] = 0u; d_h1p[0][1][i] = 0u;
        d_h1p[1][0][i] = 0u; d_h1p[1][1][i] = 0u;
        d_h2p[0][0][i] = 0u; d_h2p[0][1][i] = 0u;
        d_h2p[1][0][i] = 0u; d_h2p[1][1][i] = 0u;
    }
    if (gtid < BATCH) { d_h3[gtid] = 0.f; d_c3[gtid] = 0.f; }
    for (int idx = gtid; idx < 16 * 16 * 8 * 32; idx += NTOT) {
        int lane_ = idx & 31, nt = (idx >> 5) & 7, kt = (idx >> 8) & 15, jh = idx >> 12;
        int jg_ = jh >> 1, hf = jh & 1;
        int n = lane_ >> 2, cq = lane_ & 3;
        int up = hf * 64 + nt * 8 + n;
        int u  = (up & 3) * 256 + jg_ * 32 + (up >> 2);
        int k0 = kt * 16 + cq * 2;
        d_Bp1 [idx] = packw(Whh1, u, k0);
        d_Bp2i[idx] = packw(Wih2, u, k0);
        d_Bp2h[idx] = packw(Whh2, u, k0);
    }
    for (int i = tid; i < 4224; i += NTH) s_c1[i] = 0.f;   // zeros s_c1 and s_c2
    if (tid < 128) {
        int jl = tid >> 2, g = tid & 3;
        int u = g * 256 + jg * 32 + jl;
        s_b1[tid] = bih1[u] + bhh1[u];
        s_w1[tid] = Wih1[u];
        s_b2[tid] = bih2[u] + bhh2[u];
    }
    global_bar();   // one-time; 128 CTAs co-resident

    int parity = 0;
    for (int t = 0; t < T_STEPS + FUT; ++t) {
        unsigned* h1n_hi = &d_h1p[parity ^ 1][0][0];
        unsigned* h1n_lo = &d_h1p[parity ^ 1][1][0];
        unsigned* h2n_hi = &d_h2p[parity ^ 1][0][0];
        unsigned* h2n_lo = &d_h2p[parity ^ 1][1][0];

        // ================= phase 1 =================
        stage_copy(sAhi, sAlo, &d_h1p[parity][0][0], &d_h1p[parity][1][0], bg, tid);
        stage_copy(sBhi, sBlo, &d_h2p[parity][0][0], &d_h2p[parity][1][0], bg, tid);
        __syncthreads();
        {
            const float xin = (t < T_STEPS) ? __ldg(x + t * BATCH + b) : __ldcg(d_c3 + b);

            float acc[4][4];
            #pragma unroll
            for (int nt = 0; nt < 4; ++nt)
                #pragma unroll
                for (int q = 0; q < 4; ++q) acc[nt][q] = 0.f;

            gemm256q(acc, sAhi + moff, sAlo + moff,
                     d_Bp1 + (jgh << 12) + quad * 128, lane);

            #pragma unroll
            for (int nt = 0; nt < 4; ++nt) {
                float s0 = __shfl_xor_sync(0xffffffffu, (q4 & 1) ? acc[nt][0] : acc[nt][2], 1);
                float s1 = __shfl_xor_sync(0xffffffffu, (q4 & 1) ? acc[nt][1] : acc[nt][3], 1);
                float gi, gf, gg, go;
                if (q4 & 1) { gi = s0; gf = s1; gg = acc[nt][2]; go = acc[nt][3]; }
                else        { gi = acc[nt][0]; gf = acc[nt][1]; gg = s0; go = s1; }
                int jl = nhalf * 16 + (quad * 4 + nt) * 2 + (q4 >> 1);
                float zi = gi + xin * s_w1[jl * 4 + 0] + s_b1[jl * 4 + 0];
                float zf = gf + xin * s_w1[jl * 4 + 1] + s_b1[jl * 4 + 1];
                float zg = gg + xin * s_w1[jl * 4 + 2] + s_b1[jl * 4 + 2];
                float zo = go + xin * s_w1[jl * 4 + 3] + s_b1[jl * 4 + 3];
                int sc = rowb * 33 + jl;
                float co = s_c1[sc];
                float cn = sigf(zf) * co + sigf(zi) * tanhf_(zg);
                float hn = sigf(zo) * tanhf_(cn);
                s_c1[sc] = cn;
                float cnp = __shfl_xor_sync(0xffffffffu, cn, 2);
                float hnp = __shfl_xor_sync(0xffffffffu, hn, 2);
                if ((q4 & 2) == 0) {
                    int jp = b * 128 + jg * 16 + nhalf * 8 + (quad * 4 + nt);
                    __nv_bfloat162 ch = __floats2bfloat162_rn(cn, cnp);
                    __nv_bfloat162 cl = __floats2bfloat162_rn(cn  - __bfloat162float(ch.x),
                                                              cnp - __bfloat162float(ch.y));
                    d_c1p[0][jp] = *reinterpret_cast<unsigned*>(&ch);
                    d_c1p[1][jp] = *reinterpret_cast<unsigned*>(&cl);
                    __nv_bfloat162 hh = __floats2bfloat162_rn(hn, hnp);
                    __nv_bfloat162 hl = __floats2bfloat162_rn(hn  - __bfloat162float(hh.x),
                                                              hnp - __bfloat162float(hh.y));
                    h1n_hi[jp] = *reinterpret_cast<unsigned*>(&hh);
                    h1n_lo[jp] = *reinterpret_cast<unsigned*>(&hl);
                }
            }
        }
        cluster_bar(bg);

        // ================= phase 2 =================
        stage_copy(sAhi, sAlo, &d_c1p[0][0], &d_c1p[1][0], bg, tid);
        __syncthreads();
        {
            float acc[4][4];
            #pragma unroll
            for (int nt = 0; nt < 4; ++nt)
                #pragma unroll
                for (int q = 0; q < 4; ++q) acc[nt][q] = 0.f;

            gemm256q(acc, sAhi + moff, sAlo + moff,
                     d_Bp2i + (jgh << 12) + quad * 128, lane);
            gemm256q(acc, sBhi + moff, sBlo + moff,
                     d_Bp2h + (jgh << 12) + quad * 128, lane);

            #pragma unroll
            for (int nt = 0; nt < 4; ++nt) {
                float s0 = __shfl_xor_sync(0xffffffffu, (q4 & 1) ? acc[nt][0] : acc[nt][2], 1);
                float s1 = __shfl_xor_sync(0xffffffffu, (q4 & 1) ? acc[nt][1] : acc[nt][3], 1);
                float gi, gf, gg, go;
                if (q4 & 1) { gi = s0; gf = s1; gg = acc[nt][2]; go = acc[nt][3]; }
                else        { gi = acc[nt][0]; gf = acc[nt][1]; gg = s0; go = s1; }
                int jl = nhalf * 16 + (quad * 4 + nt) * 2 + (q4 >> 1);
                float zi = gi + s_b2[jl * 4 + 0];
                float zf = gf + s_b2[jl * 4 + 1];
                float zg = gg + s_b2[jl * 4 + 2];
                float zo = go + s_b2[jl * 4 + 3];
                int sc = rowb * 33 + jl;
                float co = s_c2[sc];
                float cn = sigf(zf) * co + sigf(zi) * tanhf_(zg);
                float hn = sigf(zo) * tanhf_(cn);
                s_c2[sc] = cn;
                float cnp = __shfl_xor_sync(0xffffffffu, cn, 2);
                float hnp = __shfl_xor_sync(0xffffffffu, hn, 2);
                if ((q4 & 2) == 0) {
                    int jp = b * 128 + jg * 16 + nhalf * 8 + (quad * 4 + nt);
                    __nv_bfloat162 ch = __floats2bfloat162_rn(cn, cnp);
                    __nv_bfloat162 cl = __floats2bfloat162_rn(cn  - __bfloat162float(ch.x),
                                                              cnp - __bfloat162float(ch.y));
                    d_c2p[0][jp] = *reinterpret_cast<unsigned*>(&ch);
                    d_c2p[1][jp] = *reinterpret_cast<unsigned*>(&cl);
                    __nv_bfloat162 hh = __floats2bfloat162_rn(hn, hnp);
                    __nv_bfloat162 hl = __floats2bfloat162_rn(hn  - __bfloat162float(hh.x),
                                                              hnp - __bfloat162float(hh.y));
                    h2n_hi[jp] = *reinterpret_cast<unsigned*>(&hh);
                    h2n_lo[jp] = *reinterpret_cast<unsigned*>(&hl);
                }
            }
        }
        cluster_bar(bg);

        // ================= phase 3 (H=1), warps 0..7, one batch row each =================
        if (warp < 8) {
            int b3 = cta * 8 + warp;
            const unsigned* c2h = &d_c2p[0][b3 * 128];
            const unsigned* c2l = &d_c2p[1][b3 * 128];
            float a0 = 0.f, a1 = 0.f, a2 = 0.f, a3 = 0.f;
            #pragma unroll
            for (int kp_i = 0; kp_i < 4; ++kp_i) {
                int kp = kp_i * 32 + lane;
                unsigned vh = __ldcg(c2h + kp);
                unsigned vl = __ldcg(c2l + kp);
                __nv_bfloat162 bh = *reinterpret_cast<__nv_bfloat162*>(&vh);
                __nv_bfloat162 bl = *reinterpret_cast<__nv_bfloat162*>(&vl);
                float v0 = __bfloat162float(bh.x) + __bfloat162float(bl.x);
                float v1 = __bfloat162float(bh.y) + __bfloat162float(bl.y);
                int k0 = kp * 2;
                a0 = fmaf(v0, Wih3[0 * H + k0], fmaf(v1, Wih3[0 * H + k0 + 1], a0));
                a1 = fmaf(v0, Wih3[1 * H + k0], fmaf(v1, Wih3[1 * H + k0 + 1], a1));
                a2 = fmaf(v0, Wih3[2 * H + k0], fmaf(v1, Wih3[2 * H + k0 + 1], a2));
                a3 = fmaf(v0, Wih3[3 * H + k0], fmaf(v1, Wih3[3 * H + k0 + 1], a3));
            }
            #pragma unroll
            for (int o = 16; o > 0; o >>= 1) {
                a0 += __shfl_xor_sync(0xFFFFFFFFu, a0, o);
                a1 += __shfl_xor_sync(0xFFFFFFFFu, a1, o);
                a2 += __shfl_xor_sync(0xFFFFFFFFu, a2, o);
                a3 += __shfl_xor_sync(0xFFFFFFFFu, a3, o);
            }
            if (lane == 0) {
                float h3o = d_h3[b3], c3o = d_c3[b3];
                float zi = a0 + h3o * Whh3[0] + bih3[0] + bhh3[0];
                float zf = a1 + h3o * Whh3[1] + bih3[1] + bhh3[1];
                float zg = a2 + h3o * Whh3[2] + bih3[2] + bhh3[2];
                float zo = a3 + h3o * Whh3[3] + bih3[3] + bhh3[3];
                float cn = sigf(zf) * c3o + sigf(zi) * tanhf_(zg);
                float hn = sigf(zo) * tanhf_(cn);
                d_c3[b3] = cn;
                d_h3[b3] = hn;
                if (t >= T_STEPS) out[b3 * FUT + (t - T_STEPS)] = cn;
            }
        }
        // c3 is consumed by phase 1 only from t = T_STEPS onward
        if (t >= T_STEPS - 1) cluster_bar(bg);

        parity ^= 1;
    }
}

extern "C" void kernel_launch(void* const* d_in, const int* in_sizes, int n_in,
                              void* d_out, int out_size) {
    (void)in_sizes; (void)n_in; (void)out_size;
    const float* x    = (const float*)d_in[0];
    const float* Wih1 = (const float*)d_in[1];
    const float* Whh1 = (const float*)d_in[2];
    const float* bih1 = (const float*)d_in[3];
    const float* bhh1 = (const float*)d_in[4];
    const float* Wih2 = (const float*)d_in[5];
    const float* Whh2 = (const float*)d_in[6];
    const float* bih2 = (const float*)d_in[7];
    const float* bhh2 = (const float*)d_in[8];
    const float* Wih3 = (const float*)d_in[9];
    const float* Whh3 = (const float*)d_in[10];
    const float* bih3 = (const float*)d_in[11];
    const float* bhh3 = (const float*)d_in[12];

    const int smem_bytes = (4 * 8448 + 2 * 2112 + 3 * 128) * 4;  // 153600
    cudaFuncSetAttribute(lstm_kernel, cudaFuncAttributeMaxDynamicSharedMemorySize, 153600);
    lstm_kernel<<<GRID, NTH, smem_bytes>>>(x, Wih1, Whh1, bih1, bhh1,
                                           Wih2, Whh2, bih2, bhh2,
                                           Wih3, Whh3, bih3, bhh3,
                                           (float*)d_out);
}